// round 7
// baseline (speedup 1.0000x reference)
#include <cuda_runtime.h>
#include <cstdint>

// CondFilterT: per row b (BATCH=16384):
//   e = table[inp[b,0]]  (64 fp32)   -> out[b, 0:64] raw
//   for c in 0..49: v = table[inp[b,1+c]]
//     filtered = v * dot(e,v) / (||e|| * ||v||^2)  -> out[b, 64+64c : 64+64(c+1)]
//
// R6: QUARTER-warp per row. Each lane owns 8 floats (2 x float4); 4 rows per
// warp (one per 8-lane quarter). Reductions are 3 butterfly levels within the
// quarter, and every SHFL instruction serves 4 rows: 75 shfl/row vs 200 in R4.
// Condition loop fully unrolled -> compile-time index-register selection and
// deep load MLP. Single wave: 4096 warps, 28 resident/SM at <=73 regs.

#define CF_BATCH  16384
#define CF_NCONDS 50
#define CF_EMB    64
#define CF_ROWLEN (CF_EMB * (1 + CF_NCONDS))   // 3264 floats per output row

__global__ __launch_bounds__(128, 7)
void condfilter_kernel(const int* __restrict__ inp,
                       const float* __restrict__ table,
                       float* __restrict__ out)
{
    const unsigned FULL = 0xFFFFFFFFu;
    const int lane  = threadIdx.x & 31;
    const int q     = lane >> 3;           // quarter id 0..3 (row within warp)
    const int ql    = lane & 7;            // lane within quarter
    const int qbase = lane & ~7;           // shfl source-lane base
    const int gwarp = (blockIdx.x * blockDim.x + threadIdx.x) >> 5;
    const int rowid = gwarp * 4 + q;       // exact: grid covers CF_BATCH rows

    // ---- 51 indices: index j lives in reg (j/8) of lane (j%8) of quarter ----
    const int* irow = inp + (size_t)rowid * (1 + CF_NCONDS);
    int idx[7];
    #pragma unroll
    for (int r = 0; r < 7; r++) {
        const int j = r * 8 + ql;
        idx[r] = (j < 1 + CF_NCONDS) ? irow[j] : 0;
    }

    const float4* __restrict__ tab = (const float4*)table;   // 16 float4 / row

    // ---- event embedding (2 x float4 per lane) + inverse norm ----
    const int e_idx = __shfl_sync(FULL, idx[0], qbase);
    const size_t eb = (size_t)e_idx * (CF_EMB / 4) + 2 * ql;
    const float4 e0 = __ldg(tab + eb);
    const float4 e1 = __ldg(tab + eb + 1);
    float ss = e0.x * e0.x + e0.y * e0.y + e0.z * e0.z + e0.w * e0.w
             + e1.x * e1.x + e1.y * e1.y + e1.z * e1.z + e1.w * e1.w;
    #pragma unroll
    for (int o = 4; o > 0; o >>= 1) ss += __shfl_xor_sync(FULL, ss, o);
    const float e_inv = rsqrtf(ss);

    float4* orow = (float4*)(out + (size_t)rowid * CF_ROWLEN);  // 816 float4
    __stcs(orow + 2 * ql,     e0);   // raw event embedding, coalesced
    __stcs(orow + 2 * ql + 1, e1);

    // ---- 50 conditions, fully unrolled (compile-time j -> reg-direct idx) ----
    #pragma unroll
    for (int c = 0; c < CF_NCONDS; c++) {
        const int j = 1 + c;
        const int cidx = __shfl_sync(FULL, idx[j >> 3], qbase + (j & 7));
        const size_t cb = (size_t)cidx * (CF_EMB / 4) + 2 * ql;
        const float4 v0 = __ldg(tab + cb);
        const float4 v1 = __ldg(tab + cb + 1);

        float s1 = v0.x * v0.x + v0.y * v0.y + v0.z * v0.z + v0.w * v0.w
                 + v1.x * v1.x + v1.y * v1.y + v1.z * v1.z + v1.w * v1.w;
        float s2 = e0.x * v0.x + e0.y * v0.y + e0.z * v0.z + e0.w * v0.w
                 + e1.x * v1.x + e1.y * v1.y + e1.z * v1.z + e1.w * v1.w;

        // 3-level butterfly within the quarter; s1/s2 independent chains
        #pragma unroll
        for (int o = 4; o > 0; o >>= 1) {
            s1 += __shfl_xor_sync(FULL, s1, o);
            s2 += __shfl_xor_sync(FULL, s2, o);
        }

        const float sc = __fdividef(s2 * e_inv, s1);   // score / ||v||
        float4 w0, w1;
        w0.x = v0.x * sc; w0.y = v0.y * sc; w0.z = v0.z * sc; w0.w = v0.w * sc;
        w1.x = v1.x * sc; w1.y = v1.y * sc; w1.z = v1.z * sc; w1.w = v1.w * sc;

        float4* oc = orow + (CF_EMB / 4) + (size_t)c * (CF_EMB / 4) + 2 * ql;
        __stcs(oc,     w0);     // 256B per quarter, coalesced across warp
        __stcs(oc + 1, w1);
    }
}

extern "C" void kernel_launch(void* const* d_in, const int* in_sizes, int n_in,
                              void* d_out, int out_size)
{
    const int*   inp   = (const int*)d_in[0];     // (16384, 51) int32
    const float* table = (const float*)d_in[1];   // (100002, 64) float32
    float*       out   = (float*)d_out;           // (16384, 3264) float32

    // 4 warps/block, 4 rows/warp -> 16 rows per 128-thread block
    const int rows_per_block = (128 / 32) * 4;
    const int grid = CF_BATCH / rows_per_block;   // 1024 (exact)
    condfilter_kernel<<<grid, 128>>>(inp, table, out);
}

// round 10
// speedup vs baseline: 1.1206x; 1.1206x over previous
#include <cuda_runtime.h>
#include <cstdint>

// CondFilterT: per row b (BATCH=16384):
//   e = table[inp[b,0]]  (64 fp32)   -> out[b, 0:64] raw
//   for c in 0..49: v = table[inp[b,1+c]]
//     filtered = v * dot(e,v) / (||e|| * ||v||^2)  -> out[b, 64+64c : 64+64(c+1)]
//
// R9 (= R8 resubmit, infra failure last round; std:: dependency removed):
// quarter-warp rows (8 lanes/row, 4 rows/warp, lane owns 2 x float4),
// ROLLED loop (prologue 2 + 16 x batch-3) to stay in L0 I$, indices staged
// in shared memory (broadcast LDS replaces SHFL.IDX + select chains),
// __launch_bounds__(256,4) caps regs at 64. Every SHFL/FMA instruction
// serves 4 rows; wavefront count per LDG/STG identical to R4.

#define CF_BATCH  16384
#define CF_NCONDS 50
#define CF_EMB    64
#define CF_ROWLEN (CF_EMB * (1 + CF_NCONDS))   // 3264 floats per output row

#define ROWS_PER_BLOCK 32                       // 256 threads / 8 lanes-per-row
#define IDX_PITCH 52                            // padded 51 -> 52

template <int N> struct BatchTag { static constexpr int value = N; };

__global__ __launch_bounds__(256, 4)
void condfilter_kernel(const int* __restrict__ inp,
                       const float* __restrict__ table,
                       float* __restrict__ out)
{
    const unsigned FULL = 0xFFFFFFFFu;
    __shared__ int sidx[ROWS_PER_BLOCK][IDX_PITCH];

    const int tid = threadIdx.x;

    // ---- cooperative coalesced load of this block's 32x51 indices ----
    {
        const int* gsrc = inp + (size_t)blockIdx.x * ROWS_PER_BLOCK * (1 + CF_NCONDS);
        #pragma unroll
        for (int i = tid; i < ROWS_PER_BLOCK * (1 + CF_NCONDS); i += 256)
            sidx[i / (1 + CF_NCONDS)][i % (1 + CF_NCONDS)] = gsrc[i];
    }
    __syncthreads();

    const int ql  = tid & 7;                    // lane within quarter (0..7)
    const int rib = tid >> 3;                   // row within block (0..31)
    const int rowid = blockIdx.x * ROWS_PER_BLOCK + rib;
    const int* __restrict__ myidx = &sidx[rib][0];

    const float4* __restrict__ tab = (const float4*)table;   // 16 float4 / row

    // ---- event embedding (2 x float4 per lane) + inverse norm ----
    const int e_idx = myidx[0];                 // broadcast LDS within quarter
    const size_t eb = (size_t)e_idx * (CF_EMB / 4) + 2 * ql;
    const float4 e0 = __ldg(tab + eb);
    const float4 e1 = __ldg(tab + eb + 1);
    float ss = e0.x * e0.x + e0.y * e0.y + e0.z * e0.z + e0.w * e0.w
             + e1.x * e1.x + e1.y * e1.y + e1.z * e1.z + e1.w * e1.w;
    #pragma unroll
    for (int o = 4; o > 0; o >>= 1) ss += __shfl_xor_sync(FULL, ss, o);
    const float e_inv = rsqrtf(ss);

    float4* orow = (float4*)(out + (size_t)rowid * CF_ROWLEN);  // 816 float4
    __stcs(orow + 2 * ql,     e0);   // raw event embedding, coalesced
    __stcs(orow + 2 * ql + 1, e1);

    // ---- condition batch processor ----
    auto do_batch = [&](int c0, auto Uc) {
        constexpr int U = decltype(Uc)::value;
        float4 v0[U], v1[U];
        #pragma unroll
        for (int u = 0; u < U; u++) {
            const int cidx = myidx[1 + c0 + u];              // broadcast LDS
            const size_t cb = (size_t)cidx * (CF_EMB / 4) + 2 * ql;
            v0[u] = __ldg(tab + cb);
            v1[u] = __ldg(tab + cb + 1);
        }
        float s1[U], s2[U];
        #pragma unroll
        for (int u = 0; u < U; u++) {
            s1[u] = v0[u].x * v0[u].x + v0[u].y * v0[u].y
                  + v0[u].z * v0[u].z + v0[u].w * v0[u].w
                  + v1[u].x * v1[u].x + v1[u].y * v1[u].y
                  + v1[u].z * v1[u].z + v1[u].w * v1[u].w;       // ||v||^2
            s2[u] = e0.x * v0[u].x + e0.y * v0[u].y
                  + e0.z * v0[u].z + e0.w * v0[u].w
                  + e1.x * v1[u].x + e1.y * v1[u].y
                  + e1.z * v1[u].z + e1.w * v1[u].w;             // dot(e,v)
        }
        // 3-level butterfly within the 8-lane quarter; 2U interleaved chains
        #pragma unroll
        for (int o = 4; o > 0; o >>= 1) {
            #pragma unroll
            for (int u = 0; u < U; u++) {
                s1[u] += __shfl_xor_sync(FULL, s1[u], o);
                s2[u] += __shfl_xor_sync(FULL, s2[u], o);
            }
        }
        #pragma unroll
        for (int u = 0; u < U; u++) {
            const float sc = __fdividef(s2[u] * e_inv, s1[u]);   // score/||v||
            float4 w0, w1;
            w0.x = v0[u].x * sc; w0.y = v0[u].y * sc;
            w0.z = v0[u].z * sc; w0.w = v0[u].w * sc;
            w1.x = v1[u].x * sc; w1.y = v1[u].y * sc;
            w1.z = v1[u].z * sc; w1.w = v1[u].w * sc;
            float4* oc = orow + (CF_EMB / 4) * (1 + c0 + u) + 2 * ql;
            __stcs(oc,     w0);
            __stcs(oc + 1, w1);
        }
    };

    // 50 conditions = prologue of 2 + 16 rolled batches of 3
    do_batch(0, BatchTag<2>{});
    for (int c0 = 2; c0 < CF_NCONDS; c0 += 3)
        do_batch(c0, BatchTag<3>{});
}

extern "C" void kernel_launch(void* const* d_in, const int* in_sizes, int n_in,
                              void* d_out, int out_size)
{
    const int*   inp   = (const int*)d_in[0];     // (16384, 51) int32
    const float* table = (const float*)d_in[1];   // (100002, 64) float32
    float*       out   = (float*)d_out;           // (16384, 3264) float32

    const int grid = CF_BATCH / ROWS_PER_BLOCK;   // 512 (exact)
    condfilter_kernel<<<grid, 256>>>(inp, table, out);
}

// round 11
// speedup vs baseline: 1.4290x; 1.2752x over previous
#include <cuda_runtime.h>
#include <cstdint>

// CondFilterT: per row b (BATCH=16384):
//   e = table[inp[b,0]]  (64 fp32)   -> out[b, 0:64] raw
//   for c in 0..49: v = table[inp[b,1+c]]
//     filtered = v * dot(e,v) / (||e|| * ||v||^2)  -> out[b, 64+64c : 64+64(c+1)]
//
// R10: R4's proven shape (half-warp rows: 2 rows/warp, float4/lane, 8192
// warps, interleaved dual-chain 4-level butterfly) at R5's occupancy:
//  - batch U=4 (cv live set 16 regs) + __launch_bounds__(128,10) -> <=51 regs,
//    40 warps/SM theoretical (R4 was 63 regs / 32 warps).
//  - indices staged in shared memory: broadcast LDS replaces SHFL.IDX +
//    select chains (frees 4 regs, cuts ALU).
//  - 128-thread blocks to smooth the wave tail.

#define CF_BATCH  16384
#define CF_NCONDS 50
#define CF_EMB    64
#define CF_ROWLEN (CF_EMB * (1 + CF_NCONDS))   // 3264 floats per output row

#define ROWS_PER_BLOCK 8                        // 4 warps x 2 rows
#define IDX_PITCH 52

template <int N> struct BatchTag { static constexpr int value = N; };

__global__ __launch_bounds__(128, 10)
void condfilter_kernel(const int* __restrict__ inp,
                       const float* __restrict__ table,
                       float* __restrict__ out)
{
    const unsigned FULL = 0xFFFFFFFFu;
    __shared__ int sidx[ROWS_PER_BLOCK][IDX_PITCH];

    const int tid = threadIdx.x;

    // ---- cooperative coalesced load of this block's 8x51 indices ----
    {
        const int* gsrc = inp + (size_t)blockIdx.x * ROWS_PER_BLOCK * (1 + CF_NCONDS);
        for (int i = tid; i < ROWS_PER_BLOCK * (1 + CF_NCONDS); i += 128)
            sidx[i / (1 + CF_NCONDS)][i % (1 + CF_NCONDS)] = gsrc[i];
    }
    __syncthreads();

    const int hl   = tid & 15;                  // lane within half-warp
    const int rib  = tid >> 4;                  // row within block (0..7)
    const int rowid = blockIdx.x * ROWS_PER_BLOCK + rib;
    const int* __restrict__ myidx = &sidx[rib][0];

    const float4* __restrict__ tab = (const float4*)table;   // 16 float4 / row

    // ---- event embedding + inverse norm (reduce over 16 lanes) ----
    const int e_idx = myidx[0];                 // broadcast LDS
    const float4 e = __ldg(tab + (size_t)e_idx * (CF_EMB / 4) + hl);
    float ss = e.x * e.x + e.y * e.y + e.z * e.z + e.w * e.w;
    #pragma unroll
    for (int o = 8; o > 0; o >>= 1) ss += __shfl_xor_sync(FULL, ss, o);
    const float e_inv = rsqrtf(ss);

    float4* orow = (float4*)(out + (size_t)rowid * CF_ROWLEN);
    __stcs(orow + hl, e);   // raw event embedding, 256B coalesced, evict-first

    // ---- condition batch processor (U conditions from cond index c0) ----
    auto do_batch = [&](int c0, auto Uc) {
        constexpr int U = decltype(Uc)::value;
        float4 cv[U];
        #pragma unroll
        for (int u = 0; u < U; u++) {
            const int cidx = myidx[1 + c0 + u];               // broadcast LDS
            cv[u] = __ldg(tab + (size_t)cidx * (CF_EMB / 4) + hl);
        }

        float s1[U], s2[U];
        #pragma unroll
        for (int u = 0; u < U; u++) {
            s1[u] = cv[u].x * cv[u].x + cv[u].y * cv[u].y
                  + cv[u].z * cv[u].z + cv[u].w * cv[u].w;     // ||v||^2
            s2[u] = e.x * cv[u].x + e.y * cv[u].y
                  + e.z * cv[u].z + e.w * cv[u].w;             // dot(e,v)
        }

        // 4-level butterfly within the half-warp; 2U interleaved chains
        #pragma unroll
        for (int o = 8; o > 0; o >>= 1) {
            #pragma unroll
            for (int u = 0; u < U; u++) {
                s1[u] += __shfl_xor_sync(FULL, s1[u], o);
                s2[u] += __shfl_xor_sync(FULL, s2[u], o);
            }
        }

        #pragma unroll
        for (int u = 0; u < U; u++) {
            const float sc = __fdividef(s2[u] * e_inv, s1[u]); // score / ||v||
            float4 w;
            w.x = cv[u].x * sc;
            w.y = cv[u].y * sc;
            w.z = cv[u].z * sc;
            w.w = cv[u].w * sc;
            __stcs(orow + 16 + (size_t)(c0 + u) * 16 + hl, w); // 256B coalesced
        }
    };

    // 50 conditions = batch of 2 + 12 rolled batches of 4
    do_batch(0, BatchTag<2>{});
    for (int c0 = 2; c0 < CF_NCONDS; c0 += 4)
        do_batch(c0, BatchTag<4>{});
}

extern "C" void kernel_launch(void* const* d_in, const int* in_sizes, int n_in,
                              void* d_out, int out_size)
{
    const int*   inp   = (const int*)d_in[0];     // (16384, 51) int32
    const float* table = (const float*)d_in[1];   // (100002, 64) float32
    float*       out   = (float*)d_out;           // (16384, 3264) float32

    const int grid = CF_BATCH / ROWS_PER_BLOCK;   // 2048 (exact)
    condfilter_kernel<<<grid, 128>>>(inp, table, out);
}

// round 12
// speedup vs baseline: 1.5230x; 1.0658x over previous
#include <cuda_runtime.h>
#include <cstdint>

// CondFilterT: per row b (BATCH=16384):
//   e = table[inp[b,0]]  (64 fp32)   -> out[b, 0:64] raw
//   for c in 0..49: v = table[inp[b,1+c]]
//     filtered = v * dot(e,v) / (||e|| * ||v||^2)  -> out[b, 64+64c : 64+64(c+1)]
//
// R11: R10 skeleton (half-warp rows, float4/lane, smem-staged indices) +
// SOFTWARE PIPELINING: double-buffered batch-4 gathers. Batch n+1's 4
// LDG.128 are issued before batch n's reduce/store, so the shuffle+store
// work hides the ~250cyc L2-hit latency and the LTS request stream stays
// dense (we're at ~86% of the measured ~6300 B/cyc LTS cap; this is the
// remaining headroom).

#define CF_BATCH  16384
#define CF_NCONDS 50
#define CF_EMB    64
#define CF_ROWLEN (CF_EMB * (1 + CF_NCONDS))   // 3264 floats per output row

#define ROWS_PER_BLOCK 8                        // 4 warps x 2 rows
#define IDX_PITCH 52

__global__ __launch_bounds__(128, 8)
void condfilter_kernel(const int* __restrict__ inp,
                       const float* __restrict__ table,
                       float* __restrict__ out)
{
    const unsigned FULL = 0xFFFFFFFFu;
    __shared__ int sidx[ROWS_PER_BLOCK][IDX_PITCH];

    const int tid = threadIdx.x;

    // ---- cooperative coalesced load of this block's 8x51 indices ----
    {
        const int* gsrc = inp + (size_t)blockIdx.x * ROWS_PER_BLOCK * (1 + CF_NCONDS);
        for (int i = tid; i < ROWS_PER_BLOCK * (1 + CF_NCONDS); i += 128)
            sidx[i / (1 + CF_NCONDS)][i % (1 + CF_NCONDS)] = gsrc[i];
    }
    __syncthreads();

    const int hl    = tid & 15;                 // lane within half-warp
    const int rib   = tid >> 4;                 // row within block (0..7)
    const int rowid = blockIdx.x * ROWS_PER_BLOCK + rib;
    const int* __restrict__ myidx = &sidx[rib][0];

    const float4* __restrict__ tab = (const float4*)table;   // 16 float4 / row

    // ---- event embedding + inverse norm (reduce over 16 lanes) ----
    const int e_idx = myidx[0];                 // broadcast LDS
    const float4 e = __ldg(tab + (size_t)e_idx * (CF_EMB / 4) + hl);
    float ss = e.x * e.x + e.y * e.y + e.z * e.z + e.w * e.w;
    #pragma unroll
    for (int o = 8; o > 0; o >>= 1) ss += __shfl_xor_sync(FULL, ss, o);
    const float e_inv = rsqrtf(ss);

    float4* orow = (float4*)(out + (size_t)rowid * CF_ROWLEN);
    __stcs(orow + hl, e);   // raw event embedding, 256B coalesced, evict-first

    // ---- reduce + scale + store a batch of U conditions held in v[] ----
    auto process = [&](const float4* v, int c0, int U_active) {
        float s1[4], s2[4];
        #pragma unroll
        for (int u = 0; u < 4; u++) {
            if (u >= U_active) break;
            s1[u] = v[u].x * v[u].x + v[u].y * v[u].y
                  + v[u].z * v[u].z + v[u].w * v[u].w;      // ||v||^2
            s2[u] = e.x * v[u].x + e.y * v[u].y
                  + e.z * v[u].z + e.w * v[u].w;            // dot(e,v)
        }
        #pragma unroll
        for (int o = 8; o > 0; o >>= 1) {
            #pragma unroll
            for (int u = 0; u < 4; u++) {
                if (u >= U_active) break;
                s1[u] += __shfl_xor_sync(FULL, s1[u], o);
                s2[u] += __shfl_xor_sync(FULL, s2[u], o);
            }
        }
        #pragma unroll
        for (int u = 0; u < 4; u++) {
            if (u >= U_active) break;
            const float sc = __fdividef(s2[u] * e_inv, s1[u]);   // score/||v||
            float4 w;
            w.x = v[u].x * sc;
            w.y = v[u].y * sc;
            w.z = v[u].z * sc;
            w.w = v[u].w * sc;
            __stcs(orow + 16 + (size_t)(c0 + u) * 16 + hl, w);   // coalesced
        }
    };

    // ---- software-pipelined condition loop ----
    // batches: [0..3],[4..7],...,[44..47] (12 x 4) then tail [48..49]
    float4 cur[4];
    #pragma unroll
    for (int u = 0; u < 4; u++)
        cur[u] = __ldg(tab + (size_t)myidx[1 + u] * (CF_EMB / 4) + hl);

    // 11 steady iterations: prefetch full next batch, process current
    for (int c0 = 0; c0 < 44; c0 += 4) {
        float4 nxt[4];
        #pragma unroll
        for (int u = 0; u < 4; u++)
            nxt[u] = __ldg(tab + (size_t)myidx[1 + c0 + 4 + u] * (CF_EMB / 4) + hl);
        process(cur, c0, 4);
        #pragma unroll
        for (int u = 0; u < 4; u++) cur[u] = nxt[u];
    }

    // penultimate: prefetch tail (2 conds), process batch at 44
    {
        float4 nxt[4];
        #pragma unroll
        for (int u = 0; u < 2; u++)
            nxt[u] = __ldg(tab + (size_t)myidx[1 + 48 + u] * (CF_EMB / 4) + hl);
        process(cur, 44, 4);
        cur[0] = nxt[0];
        cur[1] = nxt[1];
    }

    // tail: conds 48, 49
    process(cur, 48, 2);
}

extern "C" void kernel_launch(void* const* d_in, const int* in_sizes, int n_in,
                              void* d_out, int out_size)
{
    const int*   inp   = (const int*)d_in[0];     // (16384, 51) int32
    const float* table = (const float*)d_in[1];   // (100002, 64) float32
    float*       out   = (float*)d_out;           // (16384, 3264) float32

    const int grid = CF_BATCH / ROWS_PER_BLOCK;   // 2048 (exact)
    condfilter_kernel<<<grid, 128>>>(inp, table, out);
}